// round 14
// baseline (speedup 1.0000x reference)
#include <cuda_runtime.h>
#include <cstdint>

#define NSLOPE 0.2f
#define NMAX   50048
#define EMAX   655360

// ---- device scratch (no runtime allocation allowed) ----
__device__ float g_h[NMAX * 128];     // h = in @ W
__device__ float g_y[NMAX * 128];     // layer output (input to next layer)
__device__ float g_o2[NMAX * 64];     // final pre-log-softmax
__device__ float g_as[NMAX];          // h . a_src per node
__device__ float g_ad[NMAX];          // h . a_dst per node
__device__ int   g_deg[NMAX];         // in-degree (w/o self loop)
__device__ int   g_start[NMAX];       // CSR segment start (by dst)
__device__ int   g_cur[NMAX];         // scatter cursors
__device__ int   g_csr[EMAX];         // src node per CSR slot
__device__ int   g_cnt;               // global slot allocator

#define TF32_RND(u, f) asm("cvt.rna.tf32.f32 %0, %1;" : "=r"(u) : "f"(f))

// m16n8k8 tf32 HMMA, C += A*B (row.col)
__device__ __forceinline__ void mma8(float* c, const uint32_t* a, uint32_t b0, uint32_t b1) {
    asm volatile(
        "mma.sync.aligned.m16n8k8.row.col.f32.tf32.tf32.f32 "
        "{%0,%1,%2,%3}, {%4,%5,%6,%7}, {%8,%9}, {%0,%1,%2,%3};"
        : "+f"(c[0]), "+f"(c[1]), "+f"(c[2]), "+f"(c[3])
        : "r"(a[0]), "r"(a[1]), "r"(a[2]), "r"(a[3]), "r"(b0), "r"(b1));
}

// ========================== CSR build (4 kernels) ==========================

__global__ void k_zero(int n) {
    int i = blockIdx.x * 256 + threadIdx.x;
    if (i < n) g_deg[i] = 0;
    if (i == 0) g_cnt = 0;
}

__global__ void k_count(const int* __restrict__ dst, int e) {
    int i = blockIdx.x * 256 + threadIdx.x;
    if (i < e) atomicAdd(&g_deg[dst[i]], 1);
}

__global__ void k_alloc(int n) {
    __shared__ int s[256];
    __shared__ int base;
    int tid = threadIdx.x;
    int i = blockIdx.x * 256 + tid;
    int deg = (i < n) ? g_deg[i] + 1 : 0;  // +1 self loop
    s[tid] = deg;
    __syncthreads();
    for (int off = 1; off < 256; off <<= 1) {
        int a = s[tid];
        int b = (tid >= off) ? s[tid - off] : 0;
        __syncthreads();
        s[tid] = a + b;
        __syncthreads();
    }
    if (tid == 255) base = atomicAdd(&g_cnt, s[255]);
    __syncthreads();
    if (i < n) {
        int st = base + s[tid] - deg;
        g_start[i] = st;
        g_csr[st] = i;   // self-loop occupies slot 0
        g_cur[i] = 1;
    }
}

__global__ void k_scatter(const int* __restrict__ src, const int* __restrict__ dst, int e) {
    int i = blockIdx.x * 256 + threadIdx.x;
    if (i < e) {
        int d = dst[i];
        int p = atomicAdd(&g_cur[d], 1);
        g_csr[g_start[d] + p] = src[i];
    }
}

// ============ mma.sync 3xTF32 GEMM + fused attention dots ============
// H[M,BN] = A[M,128] @ W[128,BN]. Block 256 thr = 8 warps (4 x 2), tile 128 x BN.
// K chunked by 32 through smem hi/lo planes; per K-step of 8, each warp does
// 2 M-tiles x NT N-tiles x 3 split-MMAs. Epilogue computes h.a_src / h.a_dst
// from C fragments (4-lane shfl + smem atomic combine across the 2 warp cols).

template <int BN>
__global__ __launch_bounds__(256) void k_tc(
    const float* __restrict__ A, const float* __restrict__ W,
    float* __restrict__ H, const float* __restrict__ a_s,
    const float* __restrict__ a_d, int M)
{
    constexpr int ASTR = 36;          // A smem row stride (bank = 4r+k, conflict-free)
    constexpr int BSTR = BN + 8;      // B smem row stride (bank = 8k+c, conflict-free)
    constexpr int NT   = BN / 16;     // N-tiles per warp (warp covers BN/2 cols)

    extern __shared__ uint32_t smem[];
    uint32_t* Ah = smem;                    // [128][ASTR]
    uint32_t* Al = Ah + 128 * ASTR;
    uint32_t* Bh = Al + 128 * ASTR;         // [32][BSTR]
    uint32_t* Bl = Bh + 32 * BSTR;
    __shared__ float s_sa[128], s_sd[128];

    int tid = threadIdx.x, wid = tid >> 5, lane = tid & 31;
    int wm = wid >> 1, wn = wid & 1;
    int lr = lane >> 2, lk = lane & 3;
    int row0 = blockIdx.x * 128;

    float c[2][NT][4];
#pragma unroll
    for (int t = 0; t < 2; t++)
#pragma unroll
        for (int nt = 0; nt < NT; nt++)
#pragma unroll
            for (int q = 0; q < 4; q++) c[t][nt][q] = 0.f;

    if (tid < 128) {
        s_sa[tid] = 0.f;
        s_sd[tid] = 0.f;
    }

    for (int k0 = 0; k0 < 128; k0 += 32) {
        // A chunk: 128 rows x 32 k (coalesced over k), hi/lo split
        for (int i = tid; i < 128 * 32; i += 256) {
            int r = i >> 5, k = i & 31;
            int gr = row0 + r;
            float v = (gr < M) ? A[(size_t)gr * 128 + k0 + k] : 0.f;
            uint32_t hb;
            TF32_RND(hb, v);
            float hf = __uint_as_float(hb);
            uint32_t lb;
            TF32_RND(lb, v - hf);
            Ah[r * ASTR + k] = hb;
            Al[r * ASTR + k] = lb;
        }
        // B chunk: 32 k-rows x BN cols (coalesced over n), hi/lo split
        for (int i = tid; i < 32 * BN; i += 256) {
            int k = i / BN, n = i % BN;
            float v = W[(size_t)(k0 + k) * BN + n];
            uint32_t hb;
            TF32_RND(hb, v);
            float hf = __uint_as_float(hb);
            uint32_t lb;
            TF32_RND(lb, v - hf);
            Bh[k * BSTR + n] = hb;
            Bl[k * BSTR + n] = lb;
        }
        __syncthreads();
#pragma unroll
        for (int ks = 0; ks < 32; ks += 8) {
            uint32_t ah[2][4], al[2][4];
#pragma unroll
            for (int t = 0; t < 2; t++) {
                int r = wm * 32 + t * 16 + lr;
                int kk = ks + lk;
                ah[t][0] = Ah[r * ASTR + kk];
                ah[t][1] = Ah[(r + 8) * ASTR + kk];
                ah[t][2] = Ah[r * ASTR + kk + 4];
                ah[t][3] = Ah[(r + 8) * ASTR + kk + 4];
                al[t][0] = Al[r * ASTR + kk];
                al[t][1] = Al[(r + 8) * ASTR + kk];
                al[t][2] = Al[r * ASTR + kk + 4];
                al[t][3] = Al[(r + 8) * ASTR + kk + 4];
            }
#pragma unroll
            for (int nt = 0; nt < NT; nt++) {
                int cb = wn * (BN / 2) + nt * 8 + lr;
                int kk = ks + lk;
                uint32_t bh0 = Bh[kk * BSTR + cb];
                uint32_t bh1 = Bh[(kk + 4) * BSTR + cb];
                uint32_t bl0 = Bl[kk * BSTR + cb];
                uint32_t bl1 = Bl[(kk + 4) * BSTR + cb];
#pragma unroll
                for (int t = 0; t < 2; t++) {
                    mma8(c[t][nt], ah[t], bh0, bh1);   // hi*hi
                    mma8(c[t][nt], ah[t], bl0, bl1);   // hi*lo
                    mma8(c[t][nt], al[t], bh0, bh1);   // lo*hi
                }
            }
        }
        __syncthreads();
    }

    // ---- epilogue: store H, fold attention dots ----
    // C frag mapping: c0,c1 -> row lr,   cols 2*lk, 2*lk+1
    //                 c2,c3 -> row lr+8, same cols
    float sa[4] = {0.f, 0.f, 0.f, 0.f};   // [t*2 + (0: row lr, 1: row lr+8)]
    float sd[4] = {0.f, 0.f, 0.f, 0.f};
#pragma unroll
    for (int nt = 0; nt < NT; nt++) {
        int col0 = wn * (BN / 2) + nt * 8 + 2 * lk;
        float as0 = __ldg(a_s + col0), as1 = __ldg(a_s + col0 + 1);
        float ad0 = __ldg(a_d + col0), ad1 = __ldg(a_d + col0 + 1);
#pragma unroll
        for (int t = 0; t < 2; t++) {
            int rA = row0 + wm * 32 + t * 16 + lr;
            if (rA < M)
                *(float2*)(H + (size_t)rA * BN + col0) = make_float2(c[t][nt][0], c[t][nt][1]);
            if (rA + 8 < M)
                *(float2*)(H + (size_t)(rA + 8) * BN + col0) = make_float2(c[t][nt][2], c[t][nt][3]);
            sa[t * 2 + 0] += c[t][nt][0] * as0 + c[t][nt][1] * as1;
            sa[t * 2 + 1] += c[t][nt][2] * as0 + c[t][nt][3] * as1;
            sd[t * 2 + 0] += c[t][nt][0] * ad0 + c[t][nt][1] * ad1;
            sd[t * 2 + 1] += c[t][nt][2] * ad0 + c[t][nt][3] * ad1;
        }
    }
    // reduce across the 4 lanes (lk) that share each row
#pragma unroll
    for (int q = 0; q < 4; q++) {
        sa[q] += __shfl_xor_sync(0xffffffffu, sa[q], 1);
        sa[q] += __shfl_xor_sync(0xffffffffu, sa[q], 2);
        sd[q] += __shfl_xor_sync(0xffffffffu, sd[q], 1);
        sd[q] += __shfl_xor_sync(0xffffffffu, sd[q], 2);
    }
    if (lk == 0) {
#pragma unroll
        for (int t = 0; t < 2; t++) {
            int rl = wm * 32 + t * 16 + lr;
            atomicAdd(&s_sa[rl], sa[t * 2 + 0]);
            atomicAdd(&s_sd[rl], sd[t * 2 + 0]);
            atomicAdd(&s_sa[rl + 8], sa[t * 2 + 1]);
            atomicAdd(&s_sd[rl + 8], sd[t * 2 + 1]);
        }
    }
    __syncthreads();
    if (tid < 128) {
        int r = row0 + tid;
        if (r < M) {
            g_as[r] = s_sa[tid];
            g_ad[r] = s_sd[tid];
        }
    }
}

// ============ warp-per-dst-node segment softmax + weighted gather ============

template <int D, bool SILU>
__global__ void k_agg(const float* __restrict__ h, const float* __restrict__ bias,
                      float* __restrict__ out, int n) {
    constexpr int MAXDEG = 128;
    constexpr int FP = D / 32;  // floats per lane (4 or 2)
    __shared__ float wsh[8][MAXDEG];
    __shared__ int ssh[8][MAXDEG];
    int warp = threadIdx.x >> 5, lane = threadIdx.x & 31;
    int d = blockIdx.x * 8 + warp;
    if (d >= n) return;
    int st = g_start[d];
    int deg = g_deg[d] + 1;
    float ad = g_ad[d];
    int f = lane * FP;
    float acc[FP];
#pragma unroll
    for (int j = 0; j < FP; j++) acc[j] = 0.f;
    float inv;

    if (deg <= MAXDEG) {
        float m = -1e30f;
        for (int i = lane; i < deg; i += 32) {
            int s = g_csr[st + i];
            ssh[warp][i] = s;
            float al = g_as[s] + ad;
            al = al > 0.f ? al : NSLOPE * al;
            wsh[warp][i] = al;
            m = fmaxf(m, al);
        }
#pragma unroll
        for (int o = 16; o; o >>= 1) m = fmaxf(m, __shfl_xor_sync(0xffffffffu, m, o));
        __syncwarp();
        float den = 0.f;
        for (int i = lane; i < deg; i += 32) {
            float w = __expf(wsh[warp][i] - m);
            wsh[warp][i] = w;
            den += w;
        }
#pragma unroll
        for (int o = 16; o; o >>= 1) den += __shfl_xor_sync(0xffffffffu, den, o);
        __syncwarp();
        inv = 1.f / den;
        int i = 0;
        for (; i + 2 <= deg; i += 2) {
            int s0 = ssh[warp][i];
            int s1 = ssh[warp][i + 1];
            float c0 = wsh[warp][i];
            float c1 = wsh[warp][i + 1];
            const float* h0 = h + (size_t)s0 * D + f;
            const float* h1 = h + (size_t)s1 * D + f;
            if constexpr (FP == 4) {
                float4 v0 = *(const float4*)h0;
                float4 v1 = *(const float4*)h1;
                acc[0] += c0 * v0.x + c1 * v1.x;
                acc[1] += c0 * v0.y + c1 * v1.y;
                acc[2] += c0 * v0.z + c1 * v1.z;
                acc[3] += c0 * v0.w + c1 * v1.w;
            } else {
                float2 v0 = *(const float2*)h0;
                float2 v1 = *(const float2*)h1;
                acc[0] += c0 * v0.x + c1 * v1.x;
                acc[1] += c0 * v0.y + c1 * v1.y;
            }
        }
        if (i < deg) {
            int s0 = ssh[warp][i];
            float c0 = wsh[warp][i];
            const float* h0 = h + (size_t)s0 * D + f;
            if constexpr (FP == 4) {
                float4 v0 = *(const float4*)h0;
                acc[0] += c0 * v0.x;
                acc[1] += c0 * v0.y;
                acc[2] += c0 * v0.z;
                acc[3] += c0 * v0.w;
            } else {
                float2 v0 = *(const float2*)h0;
                acc[0] += c0 * v0.x;
                acc[1] += c0 * v0.y;
            }
        }
    } else {
        float m = -1e30f, den = 0.f;
        for (int i = 0; i < deg; i++) {
            int s = g_csr[st + i];
            float al = g_as[s] + ad;
            al = al > 0.f ? al : NSLOPE * al;
            float nm = fmaxf(m, al);
            float sc = __expf(m - nm);
            float w = __expf(al - nm);
            den = den * sc + w;
            const float* hp = h + (size_t)s * D + f;
#pragma unroll
            for (int j = 0; j < FP; j++) acc[j] = acc[j] * sc + w * hp[j];
            m = nm;
        }
        inv = 1.f / den;
    }

#pragma unroll
    for (int j = 0; j < FP; j++) {
        float v = acc[j] * inv + bias[f + j];
        if (SILU) v = v / (1.f + __expf(-v));
        out[(size_t)d * D + f + j] = v;
    }
}

// ========================== log_softmax over 64 cols ==========================

__global__ void k_lsm(const float* __restrict__ in, float* __restrict__ out, int n) {
    int warp = threadIdx.x >> 5, lane = threadIdx.x & 31;
    int r = blockIdx.x * 8 + warp;
    if (r >= n) return;
    float2 v = *(const float2*)&in[(size_t)r * 64 + lane * 2];
    float m = fmaxf(v.x, v.y);
#pragma unroll
    for (int o = 16; o; o >>= 1) m = fmaxf(m, __shfl_xor_sync(0xffffffffu, m, o));
    float s = __expf(v.x - m) + __expf(v.y - m);
#pragma unroll
    for (int o = 16; o; o >>= 1) s += __shfl_xor_sync(0xffffffffu, s, o);
    float l = m + __logf(s);
    float2 o2 = make_float2(v.x - l, v.y - l);
    *(float2*)&out[(size_t)r * 64 + lane * 2] = o2;
}

// ========================== host launcher ==========================

extern "C" void kernel_launch(void* const* d_in, const int* in_sizes, int n_in,
                              void* d_out, int out_size) {
    const float* x   = (const float*)d_in[0];
    const int*   ei  = (const int*)d_in[1];
    const float* W0  = (const float*)d_in[2];
    const float* as0 = (const float*)d_in[3];
    const float* ad0 = (const float*)d_in[4];
    const float* b0  = (const float*)d_in[5];
    const float* W1  = (const float*)d_in[6];
    const float* as1 = (const float*)d_in[7];
    const float* ad1 = (const float*)d_in[8];
    const float* b1  = (const float*)d_in[9];
    const float* W2  = (const float*)d_in[10];
    const float* as2 = (const float*)d_in[11];
    const float* ad2 = (const float*)d_in[12];
    const float* b2  = (const float*)d_in[13];

    int n = in_sizes[0] / 128;  // 50000
    int e = in_sizes[1] / 2;    // 600000
    const int* src = ei;
    const int* dst = ei + e;
    float* outp = (float*)d_out;

    float *ph, *py, *po2;
    cudaGetSymbolAddress((void**)&ph, g_h);
    cudaGetSymbolAddress((void**)&py, g_y);
    cudaGetSymbolAddress((void**)&po2, g_o2);

    const int SM128 = (2 * 128 * 36 + 2 * 32 * (128 + 8)) * 4;  // 71680
    const int SM64  = (2 * 128 * 36 + 2 * 32 * (64 + 8)) * 4;   // 55296
    cudaFuncSetAttribute(k_tc<128>, cudaFuncAttributeMaxDynamicSharedMemorySize, SM128);
    cudaFuncSetAttribute(k_tc<64>,  cudaFuncAttributeMaxDynamicSharedMemorySize, SM64);

    int nbN = (n + 255) / 256;
    int nbE = (e + 255) / 256;
    int nbG = (n + 127) / 128;
    int nbA = (n + 7) / 8;
    int nbW = (n + 7) / 8;

    // CSR by dst (includes self-loops at segment head)
    k_zero<<<nbN, 256>>>(n);
    k_count<<<nbE, 256>>>(dst, e);
    k_alloc<<<nbN, 256>>>(n);
    k_scatter<<<nbE, 256>>>(src, dst, e);

    // layer 0: 128 -> 128, SiLU
    k_tc<128><<<nbG, 256, SM128>>>(x, W0, ph, as0, ad0, n);
    k_agg<128, true><<<nbA, 256>>>(ph, b0, py, n);

    // layer 1: 128 -> 128, SiLU
    k_tc<128><<<nbG, 256, SM128>>>(py, W1, ph, as1, ad1, n);
    k_agg<128, true><<<nbA, 256>>>(ph, b1, py, n);

    // layer 2: 128 -> 64, no SiLU, then log_softmax
    k_tc<64><<<nbG, 256, SM64>>>(py, W2, ph, as2, ad2, n);
    k_agg<64, false><<<nbA, 256>>>(ph, b2, po2, n);
    k_lsm<<<nbW, 256>>>(po2, outp, n);
}